// round 1
// baseline (speedup 1.0000x reference)
#include <cuda_runtime.h>
#include <cstdint>

// ---------------------------------------------------------------------------
// Problem constants
// ---------------------------------------------------------------------------
constexpr int NN   = 16384;     // total nodes
constexpr int H    = 256;       // hidden
constexpr int EE   = 131072;    // edges
constexpr int DEG  = 8;
constexpr int BG   = 256;       // graphs
constexpr int NPG  = 64;        // nodes/graph
constexpr int LG   = 4;         // GAT layers

// ---------------------------------------------------------------------------
// Scratch (static device globals; allocation-free)
// ---------------------------------------------------------------------------
__device__ float g_h [NN * H];
__device__ float g_m [NN * H];
__device__ float g_q [NN * H];
__device__ float g_k [NN * H];
__device__ float g_v [NN * H];
__device__ float g_ff[NN * 2 * H];
__device__ float g_edot[LG * EE];
__device__ float g_av[132];          // [0..127] av[l][k], [128..131] bias scalar per layer
__device__ float g_gsc[NN];

// ---------------------------------------------------------------------------
// Warp reductions
// ---------------------------------------------------------------------------
__device__ __forceinline__ float wredsum(float v) {
    #pragma unroll
    for (int o = 16; o > 0; o >>= 1) v += __shfl_xor_sync(0xffffffffu, v, o);
    return v;
}

// ---------------------------------------------------------------------------
// av[l][k] = sum_j We[k,j] * gat_a[l, 2H+j] ;  bs[l] = sum_j be[j]*gat_a[l,2H+j]
// ---------------------------------------------------------------------------
__global__ void av_kernel(const float* __restrict__ We, const float* __restrict__ be,
                          const float* __restrict__ gat_a) {
    int t = threadIdx.x;
    if (t < 128) {
        int l = t >> 5, k = t & 31;
        const float* a2e = gat_a + l * 768 + 512;
        float s = 0.f;
        for (int j = 0; j < H; j++) s += We[k * H + j] * a2e[j];
        g_av[t] = s;
    } else if (t < 132) {
        int l = t - 128;
        const float* a2e = gat_a + l * 768 + 512;
        float s = 0.f;
        for (int j = 0; j < H; j++) s += be[j] * a2e[j];
        g_av[128 + l] = s;
    }
}

// edot[l][e] = bs[l] + edge_feats[e,:32] . av[l]
__global__ __launch_bounds__(256) void edot_kernel(const float* __restrict__ ef) {
    __shared__ float sav[132];
    int t = threadIdx.x;
    if (t < 132) sav[t] = g_av[t];
    __syncthreads();
    int e = blockIdx.x * 256 + t;
    float f[32];
    const float4* p = (const float4*)(ef + (size_t)e * 32);
    #pragma unroll
    for (int i = 0; i < 8; i++) {
        float4 v = p[i];
        f[4*i] = v.x; f[4*i+1] = v.y; f[4*i+2] = v.z; f[4*i+3] = v.w;
    }
    #pragma unroll
    for (int l = 0; l < LG; l++) {
        float s = sav[128 + l];
        #pragma unroll
        for (int k = 0; k < 32; k++) s += f[k] * sav[l * 32 + k];
        g_edot[l * EE + e] = s;
    }
}

// ---------------------------------------------------------------------------
// Generic fp32 GEMM: C[16384 x NDIM] = A[16384 x KDIM] @ W[KDIM x NDIM] (+bias)(+act)
// BM=128 BN=128 BK=8, 256 threads, 8x8 per thread.
// EPI: 0 none, 1 gelu(exact), 2 relu
// ---------------------------------------------------------------------------
template<int KDIM, int NDIM, int EPI>
__global__ __launch_bounds__(256) void gemm_k(const float* __restrict__ A,
                                              const float* __restrict__ W,
                                              const float* __restrict__ bias,
                                              float* __restrict__ C) {
    __shared__ float As[8][128];
    __shared__ float Bs[8][128];
    const int bm = blockIdx.y * 128;
    const int bn = blockIdx.x * 128;
    const int tid = threadIdx.x;
    const int tr = (tid >> 4) * 8;       // 0..120
    const int tc = (tid & 15) * 8;       // 0..120
    const int arow = tid >> 1, acol = (tid & 1) * 4;
    const int brow = tid >> 5, bcol = (tid & 31) * 4;

    float acc[8][8] = {};
    for (int k0 = 0; k0 < KDIM; k0 += 8) {
        float4 a4 = *(const float4*)(A + (size_t)(bm + arow) * KDIM + k0 + acol);
        As[acol + 0][arow] = a4.x;
        As[acol + 1][arow] = a4.y;
        As[acol + 2][arow] = a4.z;
        As[acol + 3][arow] = a4.w;
        float4 b4 = *(const float4*)(W + (size_t)(k0 + brow) * NDIM + bn + bcol);
        *(float4*)&Bs[brow][bcol] = b4;
        __syncthreads();
        #pragma unroll
        for (int k = 0; k < 8; k++) {
            float a[8], b[8];
            #pragma unroll
            for (int i = 0; i < 8; i++) a[i] = As[k][tr + i];
            #pragma unroll
            for (int j = 0; j < 8; j++) b[j] = Bs[k][tc + j];
            #pragma unroll
            for (int i = 0; i < 8; i++)
                #pragma unroll
                for (int j = 0; j < 8; j++)
                    acc[i][j] += a[i] * b[j];
        }
        __syncthreads();
    }

    float bv[8];
    #pragma unroll
    for (int j = 0; j < 8; j++) bv[j] = bias ? bias[bn + tc + j] : 0.f;

    #pragma unroll
    for (int i = 0; i < 8; i++) {
        float o[8];
        #pragma unroll
        for (int j = 0; j < 8; j++) {
            float v = acc[i][j] + bv[j];
            if (EPI == 1) v = 0.5f * v * (1.0f + erff(v * 0.70710678118654752f));
            else if (EPI == 2) v = fmaxf(v, 0.f);
            o[j] = v;
        }
        float* cp = C + (size_t)(bm + tr + i) * NDIM + bn + tc;
        *(float4*)(cp + 0) = make_float4(o[0], o[1], o[2], o[3]);
        *(float4*)(cp + 4) = make_float4(o[4], o[5], o[6], o[7]);
    }
}

// ---------------------------------------------------------------------------
// GAT layer: per-graph CTA. m tile in SMEM; s1/s2 per node; 8-edge softmax;
// aggregate; residual + LN (eps 1e-5) in place into g_h.
// ---------------------------------------------------------------------------
__global__ __launch_bounds__(256) void gat_kernel(int l,
                                                  const float* __restrict__ gat_a,
                                                  const float* __restrict__ gat_lng,
                                                  const float* __restrict__ gat_lnb,
                                                  const int* __restrict__ dst) {
    extern __shared__ float sm[];
    float* ms = sm;                  // [NPG*H]
    float* s1 = sm + NPG * H;        // [NPG]
    float* s2 = s1 + NPG;            // [NPG]
    const int b = blockIdx.x, tid = threadIdx.x;
    const int w = tid >> 5, lane = tid & 31;

    const float* msrc = g_m + (size_t)b * NPG * H;
    for (int i = tid * 4; i < NPG * H; i += 1024)
        *(float4*)(ms + i) = *(const float4*)(msrc + i);
    __syncthreads();

    const float* a1 = gat_a + l * 768;
    const float* a2 = a1 + H;
    for (int q = 0; q < 8; q++) {
        int nl = w * 8 + q;
        float p1 = 0.f, p2 = 0.f;
        #pragma unroll
        for (int j = 0; j < 8; j++) {
            int d = lane + 32 * j;
            float v = ms[nl * H + d];
            p1 += v * a1[d];
            p2 += v * a2[d];
        }
        p1 = wredsum(p1);
        p2 = wredsum(p2);
        if (lane == 0) { s1[nl] = p1; s2[nl] = p2; }
    }
    __syncthreads();

    const float* ed  = g_edot + (size_t)l * EE;
    const float* lgg = gat_lng + l * H;
    const float* lgb = gat_lnb + l * H;

    for (int q = 0; q < 8; q++) {
        int nl = w * 8 + q;
        int n  = b * NPG + nl;
        int eb = n * DEG;
        float s1v = s1[nl];
        float lgt[8]; int di[8];
        float mx = -1e30f;
        #pragma unroll
        for (int k = 0; k < 8; k++) {
            di[k] = dst[eb + k] - b * NPG;
            float t = s1v + s2[di[k]] + ed[eb + k];
            t = (t >= 0.f) ? t : 0.01f * t;               // LeakyReLU
            lgt[k] = t;
            mx = fmaxf(mx, t);
        }
        float den = 0.f;
        #pragma unroll
        for (int k = 0; k < 8; k++) { lgt[k] = expf(lgt[k] - mx); den += lgt[k]; }
        float inv = 1.f / den;
        #pragma unroll
        for (int k = 0; k < 8; k++) lgt[k] *= inv;

        float r[8]; float ssum = 0.f;
        #pragma unroll
        for (int j = 0; j < 8; j++) {
            int d = lane + 32 * j;
            float acc = 0.f;
            #pragma unroll
            for (int k = 0; k < 8; k++) acc += lgt[k] * ms[di[k] * H + d];
            acc += g_h[(size_t)n * H + d];
            r[j] = acc; ssum += acc;
        }
        ssum = wredsum(ssum);
        float mean = ssum * (1.f / H);
        float vv = 0.f;
        #pragma unroll
        for (int j = 0; j < 8; j++) { float t = r[j] - mean; vv += t * t; }
        vv = wredsum(vv);
        float rstd = rsqrtf(vv * (1.f / H) + 1e-5f);
        #pragma unroll
        for (int j = 0; j < 8; j++) {
            int d = lane + 32 * j;
            g_h[(size_t)n * H + d] = (r[j] - mean) * rstd * lgg[d] + lgb[d];
        }
    }
}

// ---------------------------------------------------------------------------
// Global attention: one CTA per (graph, head). q,k,v slices [64,32] in SMEM.
// Output (pre-LN) into g_m.
// ---------------------------------------------------------------------------
__global__ __launch_bounds__(256) void attn_kernel() {
    const int b = blockIdx.x >> 3, hd = blockIdx.x & 7;
    __shared__ float qs[64][33], ks[64][33], vs[64][33], ps[8][64];
    const int tid = threadIdx.x;
    const size_t base = (size_t)b * NPG * H + hd * 32;
    for (int i = tid; i < 2048; i += 256) {
        int r = i >> 5, c = i & 31;
        size_t off = base + (size_t)r * H + c;
        qs[r][c] = g_q[off];
        ks[r][c] = g_k[off];
        vs[r][c] = g_v[off];
    }
    __syncthreads();
    const int w = tid >> 5, lane = tid & 31;
    for (int q8 = 0; q8 < 8; q8++) {
        int i = w * 8 + q8;
        float s0 = 0.f, s1 = 0.f;
        #pragma unroll
        for (int d = 0; d < 32; d++) {
            float qd = qs[i][d];
            s0 += qd * ks[lane][d];
            s1 += qd * ks[lane + 32][d];
        }
        s0 *= 0.17677669529663687f;   // 1/sqrt(32)
        s1 *= 0.17677669529663687f;
        float mx = fmaxf(s0, s1);
        #pragma unroll
        for (int o = 16; o > 0; o >>= 1) mx = fmaxf(mx, __shfl_xor_sync(0xffffffffu, mx, o));
        float e0 = expf(s0 - mx), e1 = expf(s1 - mx);
        float sme = wredsum(e0 + e1);
        float inv = 1.f / sme;
        ps[w][lane]      = e0 * inv;
        ps[w][lane + 32] = e1 * inv;
        __syncwarp();
        float o = 0.f;
        #pragma unroll
        for (int j = 0; j < 64; j++) o += ps[w][j] * vs[j][lane];
        g_m[base + (size_t)i * H + lane] = o;
    }
}

// ---------------------------------------------------------------------------
// x = LayerNorm(x + y) with y=g_m, x=g_h.  One warp per node.
// ---------------------------------------------------------------------------
__global__ __launch_bounds__(256) void resln_kernel(const float* __restrict__ g,
                                                    const float* __restrict__ bt,
                                                    float eps) {
    const int w = threadIdx.x >> 5, lane = threadIdx.x & 31;
    const int n = blockIdx.x * 8 + w;
    float r[8]; float s = 0.f;
    #pragma unroll
    for (int j = 0; j < 8; j++) {
        int d = lane + 32 * j;
        float v = g_h[(size_t)n * H + d] + g_m[(size_t)n * H + d];
        r[j] = v; s += v;
    }
    s = wredsum(s);
    float mean = s * (1.f / H);
    float vv = 0.f;
    #pragma unroll
    for (int j = 0; j < 8; j++) { float t = r[j] - mean; vv += t * t; }
    vv = wredsum(vv);
    float rstd = rsqrtf(vv * (1.f / H) + eps);
    #pragma unroll
    for (int j = 0; j < 8; j++) {
        int d = lane + 32 * j;
        g_h[(size_t)n * H + d] = (r[j] - mean) * rstd * g[d] + bt[d];
    }
}

// gsc[n] = relu_out[n] . g_W2 + g_b2   (relu_out is in g_m)
__global__ __launch_bounds__(256) void gsc_kernel(const float* __restrict__ gW2,
                                                  const float* __restrict__ gb2) {
    const int w = threadIdx.x >> 5, lane = threadIdx.x & 31;
    const int n = blockIdx.x * 8 + w;
    float s = 0.f;
    #pragma unroll
    for (int j = 0; j < 8; j++) {
        int d = lane + 32 * j;
        s += g_m[(size_t)n * H + d] * gW2[d];
    }
    s = wredsum(s);
    if (lane == 0) g_gsc[n] = s + gb2[0];
}

// out[b,:] = sum_n softmax(gsc)_n * x[b*64+n,:]
__global__ __launch_bounds__(256) void readout_kernel(float* __restrict__ out) {
    const int b = blockIdx.x, tid = threadIdx.x;
    __shared__ float sg[64], pe[64];
    if (tid < 64) sg[tid] = g_gsc[b * NPG + tid];
    __syncthreads();
    if (tid < 64) {
        float mx = -1e30f;
        for (int n = 0; n < 64; n++) mx = fmaxf(mx, sg[n]);
        float se = 0.f;
        for (int n = 0; n < 64; n++) se += expf(sg[n] - mx);
        pe[tid] = expf(sg[tid] - mx) / se;
    }
    __syncthreads();
    float acc = 0.f;
    for (int n = 0; n < 64; n++)
        acc += pe[n] * g_h[(size_t)(b * NPG + n) * H + tid];
    out[b * H + tid] = acc;
}

// ---------------------------------------------------------------------------
// Launch
// ---------------------------------------------------------------------------
extern "C" void kernel_launch(void* const* d_in, const int* in_sizes, int n_in,
                              void* d_out, int out_size) {
    const float* node_feats = (const float*)d_in[0];
    const float* edge_feats = (const float*)d_in[1];
    const int*   dst        = (const int*)  d_in[3];
    const float* Wn      = (const float*)d_in[4];
    const float* bn      = (const float*)d_in[5];
    const float* We      = (const float*)d_in[6];
    const float* be      = (const float*)d_in[7];
    const float* gat_W   = (const float*)d_in[8];
    const float* gat_a   = (const float*)d_in[9];
    const float* gat_lng = (const float*)d_in[10];
    const float* gat_lnb = (const float*)d_in[11];
    const float* Wq      = (const float*)d_in[12];
    const float* Wk      = (const float*)d_in[13];
    const float* Wv      = (const float*)d_in[14];
    const float* att_lng = (const float*)d_in[15];
    const float* att_lnb = (const float*)d_in[16];
    const float* ff_W1   = (const float*)d_in[17];
    const float* ff_b1   = (const float*)d_in[18];
    const float* ff_W2   = (const float*)d_in[19];
    const float* ff_b2   = (const float*)d_in[20];
    const float* ff_lng  = (const float*)d_in[21];
    const float* ff_lnb  = (const float*)d_in[22];
    const float* gW1     = (const float*)d_in[23];
    const float* gb1     = (const float*)d_in[24];
    const float* gW2     = (const float*)d_in[25];
    const float* gb2     = (const float*)d_in[26];
    float* out = (float*)d_out;

    float *ph, *pm, *pq, *pk, *pv, *pff;
    cudaGetSymbolAddress((void**)&ph,  g_h);
    cudaGetSymbolAddress((void**)&pm,  g_m);
    cudaGetSymbolAddress((void**)&pq,  g_q);
    cudaGetSymbolAddress((void**)&pk,  g_k);
    cudaGetSymbolAddress((void**)&pv,  g_v);
    cudaGetSymbolAddress((void**)&pff, g_ff);

    const int GAT_SMEM = (NPG * H + 128) * (int)sizeof(float);   // 66048 B
    cudaFuncSetAttribute(gat_kernel, cudaFuncAttributeMaxDynamicSharedMemorySize, GAT_SMEM);

    // edge scalars (layer-folded)
    av_kernel<<<1, 160>>>(We, be, gat_a);
    edot_kernel<<<EE / 256, 256>>>(edge_feats);

    // h = node_feats @ Wn + bn
    gemm_k<64, 256, 0><<<dim3(2, 128), 256>>>(node_feats, Wn, bn, ph);

    // GAT stack
    for (int l = 0; l < LG; l++) {
        gemm_k<256, 256, 0><<<dim3(2, 128), 256>>>(ph, gat_W + (size_t)l * H * H, nullptr, pm);
        gat_kernel<<<BG, 256, GAT_SMEM>>>(l, gat_a, gat_lng, gat_lnb, dst);
    }

    // global attention
    gemm_k<256, 256, 0><<<dim3(2, 128), 256>>>(ph, Wq, nullptr, pq);
    gemm_k<256, 256, 0><<<dim3(2, 128), 256>>>(ph, Wk, nullptr, pk);
    gemm_k<256, 256, 0><<<dim3(2, 128), 256>>>(ph, Wv, nullptr, pv);
    attn_kernel<<<BG * 8, 256>>>();
    resln_kernel<<<NN / 8, 256>>>(att_lng, att_lnb, 1e-6f);

    // feed-forward
    gemm_k<256, 512, 1><<<dim3(4, 128), 256>>>(ph, ff_W1, ff_b1, pff);
    gemm_k<512, 256, 0><<<dim3(2, 128), 256>>>(pff, ff_W2, ff_b2, pm);
    resln_kernel<<<NN / 8, 256>>>(ff_lng, ff_lnb, 1e-6f);

    // gated readout
    gemm_k<256, 256, 2><<<dim3(2, 128), 256>>>(ph, gW1, gb1, pm);
    gsc_kernel<<<NN / 8, 256>>>(gW2, gb2);
    readout_kernel<<<BG, 256>>>(out);
}

// round 6
// speedup vs baseline: 1.4940x; 1.4940x over previous
#include <cuda_runtime.h>
#include <cuda_bf16.h>
#include <mma.h>
#include <cstdint>

using namespace nvcuda;

// ---------------------------------------------------------------------------
// Problem constants
// ---------------------------------------------------------------------------
constexpr int NN   = 16384;     // total nodes
constexpr int H    = 256;       // hidden
constexpr int EE   = 131072;    // edges
constexpr int DEG  = 8;
constexpr int BG   = 256;       // graphs
constexpr int NPG  = 64;        // nodes/graph
constexpr int LG   = 4;         // GAT layers

// ---------------------------------------------------------------------------
// Scratch (static device globals; allocation-free)
// ---------------------------------------------------------------------------
__device__ float g_h  [NN * H];
__device__ float g_m  [NN * H];
__device__ float g_qkv[NN * 3 * H];
__device__ float g_ff [NN * 2 * H];
__device__ float g_edot[LG * EE];
__device__ float g_av[132];
__device__ float g_gsc[NN];
__device__ __nv_bfloat16 g_bth[1 << 20];   // transposed weights, bf16 hi
__device__ __nv_bfloat16 g_btl[1 << 20];   // transposed weights, bf16 lo

// ---------------------------------------------------------------------------
// Helpers
// ---------------------------------------------------------------------------
__device__ __forceinline__ float wredsum(float v) {
    #pragma unroll
    for (int o = 16; o > 0; o >>= 1) v += __shfl_xor_sync(0xffffffffu, v, o);
    return v;
}

__device__ __forceinline__ void bf16split(float x, __nv_bfloat16& hi, __nv_bfloat16& lo) {
    hi = __float2bfloat16(x);
    lo = __float2bfloat16(x - __bfloat162float(hi));
}

// ---------------------------------------------------------------------------
// Weight preprocessing: transpose [K,N] -> [N,K], split fp32 -> bf16 hi/lo
// ---------------------------------------------------------------------------
struct WDesc { const float* src; int K; int N; int off; };
struct WTab  { WDesc w[11]; };

__global__ __launch_bounds__(256) void prep_kernel(WTab tab, int total) {
    int idx = blockIdx.x * 256 + threadIdx.x;
    if (idx >= total) return;
    int acc = 0;
    #pragma unroll
    for (int i = 0; i < 11; i++) {
        int K = tab.w[i].K, Nn = tab.w[i].N;
        int sz = K * Nn;
        if (idx < acc + sz) {
            int r = idx - acc;            // src-linear: r = k*N + n
            int k = r / Nn, n = r % Nn;
            __nv_bfloat16 hi, lo;
            bf16split(tab.w[i].src[r], hi, lo);
            int d = tab.w[i].off + n * K + k;
            g_bth[d] = hi;
            g_btl[d] = lo;
            return;
        }
        acc += sz;
    }
}

// ---------------------------------------------------------------------------
// bf16-split tensor-core GEMM:  C[16384 x ndim] = A[16384 x KDIM] @ W (+bias)(+act)
// Bth/Btl: W^T split, [ndim][KDIM] bf16.  CTA tile 128x128, 8 warps (32x64 each),
// BK=32, double-buffered SMEM, WMMA m16n16k16.  EPI: 0 none, 1 gelu, 2 relu
// ---------------------------------------------------------------------------
constexpr int LK = 48;                       // SMEM row stride (bf16 elems)
constexpr int TILE_E = 128 * LK;             // 6144 elems per operand tile
constexpr int STAGE_E = 4 * TILE_E;          // Ah, Al, Bh, Bl
constexpr int GEMM_SMEM_BYTES = 2 * STAGE_E * 2;  // 98304

template<int KDIM, int EPI>
__global__ __launch_bounds__(256) void tgemm(const float* __restrict__ A,
                                             const __nv_bfloat16* __restrict__ Bth,
                                             const __nv_bfloat16* __restrict__ Btl,
                                             const float* __restrict__ bias,
                                             float* __restrict__ C, int ndim) {
    extern __shared__ char smem_raw[];
    __nv_bfloat16* sb = (__nv_bfloat16*)smem_raw;
    __shared__ float s_bias[128];

    const int tid = threadIdx.x, wid = tid >> 5;
    const int bm = blockIdx.y * 128, bn = blockIdx.x * 128;
    const int m0 = (wid & 3) * 32, n0 = (wid >> 2) * 64;

    if (tid < 128) s_bias[tid] = bias ? bias[bn + tid] : 0.f;

    // register staging
    float4 aR[4];
    uint4  bhR[2], blR[2];
    const int a_r0 = tid >> 3, a_kc = (tid & 7) * 4;

    auto ldg = [&](int c) {
        #pragma unroll
        for (int i = 0; i < 4; i++) {
            int r = a_r0 + i * 32;
            aR[i] = *(const float4*)(A + (size_t)(bm + r) * KDIM + c * 32 + a_kc);
        }
        #pragma unroll
        for (int i = 0; i < 2; i++) {
            int lin = tid + i * 256;
            int n = lin >> 2, k8 = (lin & 3) * 8;
            size_t g = (size_t)(bn + n) * KDIM + c * 32 + k8;
            bhR[i] = *(const uint4*)(Bth + g);
            blR[i] = *(const uint4*)(Btl + g);
        }
    };
    auto sts = [&](int s) {
        __nv_bfloat16* Ah = sb + s * STAGE_E;
        __nv_bfloat16* Al = Ah + TILE_E;
        __nv_bfloat16* Bh = Ah + 2 * TILE_E;
        __nv_bfloat16* Bl = Ah + 3 * TILE_E;
        #pragma unroll
        for (int i = 0; i < 4; i++) {
            int r = a_r0 + i * 32;
            __nv_bfloat16 h[4], l[4];
            bf16split(aR[i].x, h[0], l[0]); bf16split(aR[i].y, h[1], l[1]);
            bf16split(aR[i].z, h[2], l[2]); bf16split(aR[i].w, h[3], l[3]);
            *(uint2*)(Ah + r * LK + a_kc) = *(uint2*)h;
            *(uint2*)(Al + r * LK + a_kc) = *(uint2*)l;
        }
        #pragma unroll
        for (int i = 0; i < 2; i++) {
            int lin = tid + i * 256;
            int n = lin >> 2, k8 = (lin & 3) * 8;
            *(uint4*)(Bh + n * LK + k8) = bhR[i];
            *(uint4*)(Bl + n * LK + k8) = blR[i];
        }
    };

    wmma::fragment<wmma::accumulator, 16, 16, 16, float> acc[2][4];
    #pragma unroll
    for (int m = 0; m < 2; m++)
        #pragma unroll
        for (int n = 0; n < 4; n++) wmma::fill_fragment(acc[m][n], 0.f);

    constexpr int NC = KDIM / 32;
    ldg(0); sts(0);
    __syncthreads();

    for (int c = 0; c < NC; c++) {
        if (c + 1 < NC) ldg(c + 1);
        const __nv_bfloat16* Ah = sb + (c & 1) * STAGE_E;
        const __nv_bfloat16* Al = Ah + TILE_E;
        const __nv_bfloat16* Bh = Ah + 2 * TILE_E;
        const __nv_bfloat16* Bl = Ah + 3 * TILE_E;
        #pragma unroll
        for (int k2 = 0; k2 < 2; k2++) {
            const int kk = k2 * 16;
            wmma::fragment<wmma::matrix_a, 16, 16, 16, __nv_bfloat16, wmma::row_major> ah0, ah1, al0, al1;
            wmma::load_matrix_sync(ah0, Ah + (m0     ) * LK + kk, LK);
            wmma::load_matrix_sync(ah1, Ah + (m0 + 16) * LK + kk, LK);
            wmma::load_matrix_sync(al0, Al + (m0     ) * LK + kk, LK);
            wmma::load_matrix_sync(al1, Al + (m0 + 16) * LK + kk, LK);
            #pragma unroll
            for (int nn = 0; nn < 4; nn++) {
                wmma::fragment<wmma::matrix_b, 16, 16, 16, __nv_bfloat16, wmma::col_major> bh, bl;
                wmma::load_matrix_sync(bh, Bh + (n0 + nn * 16) * LK + kk, LK);
                wmma::load_matrix_sync(bl, Bl + (n0 + nn * 16) * LK + kk, LK);
                wmma::mma_sync(acc[0][nn], ah0, bh, acc[0][nn]);
                wmma::mma_sync(acc[1][nn], ah1, bh, acc[1][nn]);
                wmma::mma_sync(acc[0][nn], ah0, bl, acc[0][nn]);
                wmma::mma_sync(acc[1][nn], ah1, bl, acc[1][nn]);
                wmma::mma_sync(acc[0][nn], al0, bh, acc[0][nn]);
                wmma::mma_sync(acc[1][nn], al1, bh, acc[1][nn]);
            }
        }
        if (c + 1 < NC) sts((c + 1) & 1);
        __syncthreads();
    }

    // epilogue: stage accumulators through SMEM, apply bias/act, coalesced stores
    float* Cs = (float*)smem_raw;                 // [128][132]
    #pragma unroll
    for (int m = 0; m < 2; m++)
        #pragma unroll
        for (int n = 0; n < 4; n++)
            wmma::store_matrix_sync(Cs + (m0 + m * 16) * 132 + n0 + n * 16,
                                    acc[m][n], 132, wmma::mem_row_major);
    __syncthreads();

    #pragma unroll
    for (int i = 0; i < 16; i++) {
        int idx4 = tid + i * 256;
        int r = idx4 >> 5, c4 = (idx4 & 31) * 4;
        float4 v = *(float4*)(Cs + r * 132 + c4);
        v.x += s_bias[c4 + 0]; v.y += s_bias[c4 + 1];
        v.z += s_bias[c4 + 2]; v.w += s_bias[c4 + 3];
        if (EPI == 1) {
            v.x = 0.5f * v.x * (1.f + erff(v.x * 0.70710678118654752f));
            v.y = 0.5f * v.y * (1.f + erff(v.y * 0.70710678118654752f));
            v.z = 0.5f * v.z * (1.f + erff(v.z * 0.70710678118654752f));
            v.w = 0.5f * v.w * (1.f + erff(v.w * 0.70710678118654752f));
        } else if (EPI == 2) {
            v.x = fmaxf(v.x, 0.f); v.y = fmaxf(v.y, 0.f);
            v.z = fmaxf(v.z, 0.f); v.w = fmaxf(v.w, 0.f);
        }
        *(float4*)(C + (size_t)(bm + r) * ndim + bn + c4) = v;
    }
}

// ---------------------------------------------------------------------------
// av[l][k] = sum_j We[k,j] * gat_a[l, 2H+j] ;  bs[l] = sum_j be[j]*gat_a[l,2H+j]
// ---------------------------------------------------------------------------
__global__ void av_kernel(const float* __restrict__ We, const float* __restrict__ be,
                          const float* __restrict__ gat_a) {
    int t = threadIdx.x;
    if (t < 128) {
        int l = t >> 5, k = t & 31;
        const float* a2e = gat_a + l * 768 + 512;
        float s = 0.f;
        for (int j = 0; j < H; j++) s += We[k * H + j] * a2e[j];
        g_av[t] = s;
    } else if (t < 132) {
        int l = t - 128;
        const float* a2e = gat_a + l * 768 + 512;
        float s = 0.f;
        for (int j = 0; j < H; j++) s += be[j] * a2e[j];
        g_av[128 + l] = s;
    }
}

__global__ __launch_bounds__(256) void edot_kernel(const float* __restrict__ ef) {
    __shared__ float sav[132];
    int t = threadIdx.x;
    if (t < 132) sav[t] = g_av[t];
    __syncthreads();
    int e = blockIdx.x * 256 + t;
    float f[32];
    const float4* p = (const float4*)(ef + (size_t)e * 32);
    #pragma unroll
    for (int i = 0; i < 8; i++) {
        float4 v = p[i];
        f[4*i] = v.x; f[4*i+1] = v.y; f[4*i+2] = v.z; f[4*i+3] = v.w;
    }
    #pragma unroll
    for (int l = 0; l < LG; l++) {
        float s = sav[128 + l];
        #pragma unroll
        for (int k = 0; k < 32; k++) s += f[k] * sav[l * 32 + k];
        g_edot[l * EE + e] = s;
    }
}

// ---------------------------------------------------------------------------
// GAT layer (per-graph CTA), residual+LN in place into g_h
// ---------------------------------------------------------------------------
__global__ __launch_bounds__(256) void gat_kernel(int l,
                                                  const float* __restrict__ gat_a,
                                                  const float* __restrict__ gat_lng,
                                                  const float* __restrict__ gat_lnb,
                                                  const int* __restrict__ dst) {
    extern __shared__ float sm[];
    float* ms = sm;
    float* s1 = sm + NPG * H;
    float* s2 = s1 + NPG;
    const int b = blockIdx.x, tid = threadIdx.x;
    const int w = tid >> 5, lane = tid & 31;

    const float* msrc = g_m + (size_t)b * NPG * H;
    for (int i = tid * 4; i < NPG * H; i += 1024)
        *(float4*)(ms + i) = *(const float4*)(msrc + i);
    __syncthreads();

    const float* a1 = gat_a + l * 768;
    const float* a2 = a1 + H;
    for (int q = 0; q < 8; q++) {
        int nl = w * 8 + q;
        float p1 = 0.f, p2 = 0.f;
        #pragma unroll
        for (int j = 0; j < 8; j++) {
            int d = lane + 32 * j;
            float v = ms[nl * H + d];
            p1 += v * a1[d];
            p2 += v * a2[d];
        }
        p1 = wredsum(p1);
        p2 = wredsum(p2);
        if (lane == 0) { s1[nl] = p1; s2[nl] = p2; }
    }
    __syncthreads();

    const float* ed  = g_edot + (size_t)l * EE;
    const float* lgg = gat_lng + l * H;
    const float* lgb = gat_lnb + l * H;

    for (int q = 0; q < 8; q++) {
        int nl = w * 8 + q;
        int n  = b * NPG + nl;
        int eb = n * DEG;
        float s1v = s1[nl];
        float lgt[8]; int di[8];
        float mx = -1e30f;
        #pragma unroll
        for (int k = 0; k < 8; k++) {
            di[k] = dst[eb + k] - b * NPG;
            float t = s1v + s2[di[k]] + ed[eb + k];
            t = (t >= 0.f) ? t : 0.01f * t;
            lgt[k] = t;
            mx = fmaxf(mx, t);
        }
        float den = 0.f;
        #pragma unroll
        for (int k = 0; k < 8; k++) { lgt[k] = expf(lgt[k] - mx); den += lgt[k]; }
        float inv = 1.f / den;
        #pragma unroll
        for (int k = 0; k < 8; k++) lgt[k] *= inv;

        float r[8]; float ssum = 0.f;
        #pragma unroll
        for (int j = 0; j < 8; j++) {
            int d = lane + 32 * j;
            float acc = 0.f;
            #pragma unroll
            for (int k = 0; k < 8; k++) acc += lgt[k] * ms[di[k] * H + d];
            acc += g_h[(size_t)n * H + d];
            r[j] = acc; ssum += acc;
        }
        ssum = wredsum(ssum);
        float mean = ssum * (1.f / H);
        float vv = 0.f;
        #pragma unroll
        for (int j = 0; j < 8; j++) { float t = r[j] - mean; vv += t * t; }
        vv = wredsum(vv);
        float rstd = rsqrtf(vv * (1.f / H) + 1e-5f);
        #pragma unroll
        for (int j = 0; j < 8; j++) {
            int d = lane + 32 * j;
            g_h[(size_t)n * H + d] = (r[j] - mean) * rstd * lgg[d] + lgb[d];
        }
    }
}

// ---------------------------------------------------------------------------
// Global attention: one CTA per (graph, head); reads fused qkv buffer
// ---------------------------------------------------------------------------
__global__ __launch_bounds__(256) void attn_kernel() {
    const int b = blockIdx.x >> 3, hd = blockIdx.x & 7;
    __shared__ float qs[64][33], ks[64][33], vs[64][33], ps[8][64];
    const int tid = threadIdx.x;
    for (int i = tid; i < 2048; i += 256) {
        int r = i >> 5, c = i & 31;
        size_t off = (size_t)(b * NPG + r) * 768 + hd * 32 + c;
        qs[r][c] = g_qkv[off];
        ks[r][c] = g_qkv[off + 256];
        vs[r][c] = g_qkv[off + 512];
    }
    __syncthreads();
    const int w = tid >> 5, lane = tid & 31;
    const size_t obase = (size_t)b * NPG * H + hd * 32;
    for (int q8 = 0; q8 < 8; q8++) {
        int i = w * 8 + q8;
        float s0 = 0.f, s1 = 0.f;
        #pragma unroll
        for (int d = 0; d < 32; d++) {
            float qd = qs[i][d];
            s0 += qd * ks[lane][d];
            s1 += qd * ks[lane + 32][d];
        }
        s0 *= 0.17677669529663687f;
        s1 *= 0.17677669529663687f;
        float mx = fmaxf(s0, s1);
        #pragma unroll
        for (int o = 16; o > 0; o >>= 1) mx = fmaxf(mx, __shfl_xor_sync(0xffffffffu, mx, o));
        float e0 = expf(s0 - mx), e1 = expf(s1 - mx);
        float sme = wredsum(e0 + e1);
        float inv = 1.f / sme;
        ps[w][lane]      = e0 * inv;
        ps[w][lane + 32] = e1 * inv;
        __syncwarp();
        float o = 0.f;
        #pragma unroll
        for (int j = 0; j < 64; j++) o += ps[w][j] * vs[j][lane];
        g_m[obase + (size_t)i * H + lane] = o;
    }
}

// ---------------------------------------------------------------------------
// x = LayerNorm(x + y), y=g_m, x=g_h
// ---------------------------------------------------------------------------
__global__ __launch_bounds__(256) void resln_kernel(const float* __restrict__ g,
                                                    const float* __restrict__ bt,
                                                    float eps) {
    const int w = threadIdx.x >> 5, lane = threadIdx.x & 31;
    const int n = blockIdx.x * 8 + w;
    float r[8]; float s = 0.f;
    #pragma unroll
    for (int j = 0; j < 8; j++) {
        int d = lane + 32 * j;
        float v = g_h[(size_t)n * H + d] + g_m[(size_t)n * H + d];
        r[j] = v; s += v;
    }
    s = wredsum(s);
    float mean = s * (1.f / H);
    float vv = 0.f;
    #pragma unroll
    for (int j = 0; j < 8; j++) { float t = r[j] - mean; vv += t * t; }
    vv = wredsum(vv);
    float rstd = rsqrtf(vv * (1.f / H) + eps);
    #pragma unroll
    for (int j = 0; j < 8; j++) {
        int d = lane + 32 * j;
        g_h[(size_t)n * H + d] = (r[j] - mean) * rstd * g[d] + bt[d];
    }
}

__global__ __launch_bounds__(256) void gsc_kernel(const float* __restrict__ gW2,
                                                  const float* __restrict__ gb2) {
    const int w = threadIdx.x >> 5, lane = threadIdx.x & 31;
    const int n = blockIdx.x * 8 + w;
    float s = 0.f;
    #pragma unroll
    for (int j = 0; j < 8; j++) {
        int d = lane + 32 * j;
        s += g_m[(size_t)n * H + d] * gW2[d];
    }
    s = wredsum(s);
    if (lane == 0) g_gsc[n] = s + gb2[0];
}

__global__ __launch_bounds__(256) void readout_kernel(float* __restrict__ out) {
    const int b = blockIdx.x, tid = threadIdx.x;
    __shared__ float sg[64], pe[64];
    if (tid < 64) sg[tid] = g_gsc[b * NPG + tid];
    __syncthreads();
    if (tid < 64) {
        float mx = -1e30f;
        for (int n = 0; n < 64; n++) mx = fmaxf(mx, sg[n]);
        float se = 0.f;
        for (int n = 0; n < 64; n++) se += expf(sg[n] - mx);
        pe[tid] = expf(sg[tid] - mx) / se;
    }
    __syncthreads();
    float acc = 0.f;
    for (int n = 0; n < 64; n++)
        acc += pe[n] * g_h[(size_t)(b * NPG + n) * H + tid];
    out[b * H + tid] = acc;
}

// ---------------------------------------------------------------------------
// Launch
// ---------------------------------------------------------------------------
extern "C" void kernel_launch(void* const* d_in, const int* in_sizes, int n_in,
                              void* d_out, int out_size) {
    const float* node_feats = (const float*)d_in[0];
    const float* edge_feats = (const float*)d_in[1];
    const int*   dst        = (const int*)  d_in[3];
    const float* Wn      = (const float*)d_in[4];
    const float* bn      = (const float*)d_in[5];
    const float* We      = (const float*)d_in[6];
    const float* be      = (const float*)d_in[7];
    const float* gat_W   = (const float*)d_in[8];
    const float* gat_a   = (const float*)d_in[9];
    const float* gat_lng = (const float*)d_in[10];
    const float* gat_lnb = (const float*)d_in[11];
    const float* Wq      = (const float*)d_in[12];
    const float* Wk      = (const float*)d_in[13];
    const float* Wv      = (const float*)d_in[14];
    const float* att_lng = (const float*)d_in[15];
    const float* att_lnb = (const float*)d_in[16];
    const float* ff_W1   = (const float*)d_in[17];
    const float* ff_b1   = (const float*)d_in[18];
    const float* ff_W2   = (const float*)d_in[19];
    const float* ff_b2   = (const float*)d_in[20];
    const float* ff_lng  = (const float*)d_in[21];
    const float* ff_lnb  = (const float*)d_in[22];
    const float* gW1     = (const float*)d_in[23];
    const float* gb1     = (const float*)d_in[24];
    const float* gW2     = (const float*)d_in[25];
    const float* gb2     = (const float*)d_in[26];
    float* out = (float*)d_out;

    float *ph, *pm, *pqkv, *pff;
    __nv_bfloat16 *pwh, *pwl;
    cudaGetSymbolAddress((void**)&ph,   g_h);
    cudaGetSymbolAddress((void**)&pm,   g_m);
    cudaGetSymbolAddress((void**)&pqkv, g_qkv);
    cudaGetSymbolAddress((void**)&pff,  g_ff);
    cudaGetSymbolAddress((void**)&pwh,  g_bth);
    cudaGetSymbolAddress((void**)&pwl,  g_btl);

    // weight offsets in the transposed/split buffers
    const int O_WN = 0;                       // 64x256   -> 16384
    const int O_G0 = 16384, O_G1 = 81920, O_G2 = 147456, O_G3 = 212992;
    const int O_QKV = 278528;                 // 3 x 256x256 concatenated along N
    const int O_F1 = 475136;                  // 256x512
    const int O_F2 = 606208;                  // 512x256
    const int O_GW = 737280;                  // 256x256
    WTab tab;
    tab.w[0]  = { Wn,              64,  256, O_WN };
    tab.w[1]  = { gat_W + 0*65536, 256, 256, O_G0 };
    tab.w[2]  = { gat_W + 1*65536, 256, 256, O_G1 };
    tab.w[3]  = { gat_W + 2*65536, 256, 256, O_G2 };
    tab.w[4]  = { gat_W + 3*65536, 256, 256, O_G3 };
    tab.w[5]  = { Wq,              256, 256, O_QKV };
    tab.w[6]  = { Wk,              256, 256, O_QKV + 65536 };
    tab.w[7]  = { Wv,              256, 256, O_QKV + 131072 };
    tab.w[8]  = { ff_W1,           256, 512, O_F1 };
    tab.w[9]  = { ff_W2,           512, 256, O_F2 };
    tab.w[10] = { gW1,             256, 256, O_GW };
    const int TOTAL_W = 802816;

    cudaFuncSetAttribute(tgemm<64, 0>,  cudaFuncAttributeMaxDynamicSharedMemorySize, GEMM_SMEM_BYTES);
    cudaFuncSetAttribute(tgemm<256, 0>, cudaFuncAttributeMaxDynamicSharedMemorySize, GEMM_SMEM_BYTES);
    cudaFuncSetAttribute(tgemm<256, 1>, cudaFuncAttributeMaxDynamicSharedMemorySize, GEMM_SMEM_BYTES);
    cudaFuncSetAttribute(tgemm<256, 2>, cudaFuncAttributeMaxDynamicSharedMemorySize, GEMM_SMEM_BYTES);
    cudaFuncSetAttribute(tgemm<512, 0>, cudaFuncAttributeMaxDynamicSharedMemorySize, GEMM_SMEM_BYTES);
    const int GAT_SMEM = (NPG * H + 128) * (int)sizeof(float);
    cudaFuncSetAttribute(gat_kernel, cudaFuncAttributeMaxDynamicSharedMemorySize, GAT_SMEM);

    // preprocess weights + edge scalars
    prep_kernel<<<(TOTAL_W + 255) / 256, 256>>>(tab, TOTAL_W);
    av_kernel<<<1, 160>>>(We, be, gat_a);
    edot_kernel<<<EE / 256, 256>>>(edge_feats);

    // h = node_feats @ Wn + bn
    tgemm<64, 0><<<dim3(2, 128), 256, GEMM_SMEM_BYTES>>>(node_feats, pwh + O_WN, pwl + O_WN, bn, ph, 256);

    // GAT stack
    const int OG[4] = { O_G0, O_G1, O_G2, O_G3 };
    for (int l = 0; l < LG; l++) {
        tgemm<256, 0><<<dim3(2, 128), 256, GEMM_SMEM_BYTES>>>(ph, pwh + OG[l], pwl + OG[l], nullptr, pm, 256);
        gat_kernel<<<BG, 256, GAT_SMEM>>>(l, gat_a, gat_lng, gat_lnb, dst);
    }

    // global attention (fused QKV)
    tgemm<256, 0><<<dim3(6, 128), 256, GEMM_SMEM_BYTES>>>(ph, pwh + O_QKV, pwl + O_QKV, nullptr, pqkv, 768);
    attn_kernel<<<BG * 8, 256>>>();
    resln_kernel<<<NN / 8, 256>>>(att_lng, att_lnb, 1e-6f);

    // feed-forward
    tgemm<256, 1><<<dim3(4, 128), 256, GEMM_SMEM_BYTES>>>(ph, pwh + O_F1, pwl + O_F1, ff_b1, pff, 512);
    tgemm<512, 0><<<dim3(2, 128), 256, GEMM_SMEM_BYTES>>>(pff, pwh + O_F2, pwl + O_F2, ff_b2, pm, 256);
    resln_kernel<<<NN / 8, 256>>>(ff_lng, ff_lnb, 1e-6f);

    // gated readout
    tgemm<256, 2><<<dim3(2, 128), 256, GEMM_SMEM_BYTES>>>(ph, pwh + O_GW, pwl + O_GW, gb1, pm, 256);
    gsc_kernel<<<NN / 8, 256>>>(gW2, gb2);
    readout_kernel<<<BG, 256>>>(out);
}